// round 17
// baseline (speedup 1.0000x reference)
#include <cuda_runtime.h>
#include <cstdint>

// Haar 2x2 wavelet: in (16,32,512,512) f32 -> out (16,128,256,256) f32
// out[b][0*32+c] = pooled, [1*32+c] = diff_h, [2*32+c] = diff_v, [3*32+c] = diff_d
//
// FINAL — converged (11 reproductions: kernel 149.1-150.8 us, harness
// 156.3-157.8 us, DRAM 85.4-86.2%, 6.8 TB/s; SM-side effective ~7.1 TB/s
// = 89% of 8 TB/s pin spec). Traffic compulsory-minimal: 512 MiB read
// once + 512 MiB written once, LDG.128/STG.128, zero over-fetch.
// L2 = 40%, L1 = 40%, issue = 11.5%, fma = 7.4%, regs = 31 — every
// on-chip resource has >2x headroom; the binding constraint is DRAM
// read/write-turnaround for a balanced 1:1 stream.
//
// Closed search space:
//   - 2x per-thread tile (MLP 4->8): -12% (regs 48, occ 49%)
//   - __ldcs/__stcs evict-first (both/load-only): -1.5..-11%
//   - persistent grid-stride: -11% (per-warp load cadence)
//   - block 128/512: neutral
//   - butterfly arithmetic (kept): neutral, -33% FADDs, rel_err 4.5e-8
//   - load split-sector repack: rejected by model (L1tex non-binding at
//     40%; fix would narrow stores or add smem stage on the binding path)

#define B_  16
#define C_  32
#define H_  512
#define W_  512
#define HO_ 256
#define WO_ 256

__global__ __launch_bounds__(256) void haar_kernel(
    const float* __restrict__ x, float* __restrict__ out)
{
    // One thread = 4 output pixels (float4 wide) at (bc, h, w4*4..w4*4+3)
    // total threads = B*C*HO*(WO/4) = 16*32*256*64 = 8,388,608
    const uint32_t t = blockIdx.x * blockDim.x + threadIdx.x;

    const uint32_t w4  = t & 63u;          // WO/4 = 64
    uint32_t tmp       = t >> 6;
    const uint32_t h   = tmp & 255u;       // HO = 256
    const uint32_t bc  = tmp >> 8;         // 0..511 (b*C + c)

    // ---- input loads: rows 2h and 2h+1, cols 8*w4 .. 8*w4+7 ----
    const float* row0 = x + ((size_t)bc * (H_ * W_)) + (size_t)(2u * h) * W_ + w4 * 8u;
    const float* row1 = row0 + W_;

    const float4 t0 = *reinterpret_cast<const float4*>(row0);
    const float4 t1 = *reinterpret_cast<const float4*>(row0 + 4);
    const float4 b0 = *reinterpret_cast<const float4*>(row1);
    const float4 b1 = *reinterpret_cast<const float4*>(row1 + 4);

    float4 pooled, dh, dv, dd;

    // Butterfly per quad: (a,b) = top pair, (c,d) = bottom pair.
    #define HAARQ(a_, b_, c_, d_, i)                 \
    {                                                \
        const float s0 = (a_) + (b_);                \
        const float s1 = (c_) + (d_);                \
        const float g0 = (a_) - (b_);                \
        const float g1 = (c_) - (d_);                \
        pooled.i = (s0 + s1) * 0.25f;                \
        dh.i     = (s0 - s1) * 0.5f;                 \
        dv.i     = (g0 + g1) * 0.5f;                 \
        dd.i     =  g0 - g1;                         \
    }

    HAARQ(t0.x, t0.y, b0.x, b0.y, x)
    HAARQ(t0.z, t0.w, b0.z, b0.w, y)
    HAARQ(t1.x, t1.y, b1.x, b1.y, z)
    HAARQ(t1.z, t1.w, b1.z, b1.w, w)
    #undef HAARQ

    // ---- output stores ----
    const uint32_t b_idx = bc >> 5;        // /32
    const uint32_t ch    = bc & 31u;       // %32
    // out[b][g*32+ch][h][w]; plane = HO*WO = 65536
    const size_t plane = (size_t)HO_ * WO_;
    float* obase = out + ((size_t)b_idx * (4 * C_) + ch) * plane
                       + (size_t)h * WO_ + w4 * 4u;

    *reinterpret_cast<float4*>(obase)                   = pooled;  // group 0
    *reinterpret_cast<float4*>(obase + 1 * C_ * plane)  = dh;      // group 1
    *reinterpret_cast<float4*>(obase + 2 * C_ * plane)  = dv;      // group 2
    *reinterpret_cast<float4*>(obase + 3 * C_ * plane)  = dd;      // group 3
}

extern "C" void kernel_launch(void* const* d_in, const int* in_sizes, int n_in,
                              void* d_out, int out_size)
{
    const float* x = (const float*)d_in[0];
    float* out = (float*)d_out;

    const uint32_t total_threads = B_ * C_ * HO_ * (WO_ / 4);  // 8,388,608
    const uint32_t block = 256;
    const uint32_t grid = total_threads / block;               // 32768

    haar_kernel<<<grid, block>>>(x, out);
}